// round 4
// baseline (speedup 1.0000x reference)
#include <cuda_runtime.h>

#define NQ 14

// Analytic transfer-matrix evaluation of the QuantumGate circuit.
//
// Derivation: the CNOT chain (control w, target w+1, w increasing) maps basis
// |b> -> |b'> with b'_k = XOR_{j<=k} b_j (a permutation P). The state before
// the first chain is a product state |psi1> = (x) phi_q with
//   phi_q = RY(p0_q) RX(x_q)|0> = [c1*cx + i*s1*sx,  s1*cx - i*c1*sx]
// (c1=cos(p0/2), s1=sin(p0/2), cx=cos(x/2), sx=sin(x/2)).
// Final state = P U2 P |psi1>, U2 = (x) RY(p1_q). Using P^t Z_w P = Z_0..Z_w
// and RY^t Z RY = cos(p1) Z - sin(p1) X =: M_q:
//   <Z_w> = <psi1| P^t ((x)_{q<=w} M_q) P |psi1>
// P|psi1> has amplitudes prod_q phi_q(b_q ^ b_{q-1}) (nearest-neighbor chain),
// so each expectation is a 2x2 Hermitian transfer-matrix recursion:
//   W_{-1} = [[1,0],[0,0]]
//   W_q    = M_q  (Hadamard)  ( conj(Phi_q) W_{q-1} Phi_q ),
//            Phi_q = [[phi0, phi1],[phi1, phi0]]  (symmetric)
//   <Z_w>  = W_w[00] + W_w[11] + rho_w * 2*Re(W_w[01])
//   rho_w  = 2*Re(conj(phi0_{w+1}) phi1_{w+1}) = sin(p0_{w+1})*cos(x_{w+1})
//            for w < 13;   rho_13 = 1.
// (Identity qubits beyond w+1 collapse to [1,1] by normalization.)

__global__ void __launch_bounds__(128)
quantum_gate_kernel(const float* __restrict__ x,
                    const float* __restrict__ params,
                    float* __restrict__ out, int B)
{
    int b = blockIdx.x * blockDim.x + threadIdx.x;
    if (b >= B) return;

    // Per-qubit shared-parameter trig (identical across threads; trivially cheap)
    float c1[NQ], s1[NQ], Cc[NQ], Ss[NQ];
#pragma unroll
    for (int q = 0; q < NQ; q++) {
        float p0 = __ldg(&params[q]);
        float p1 = __ldg(&params[NQ + q]);
        __sincosf(0.5f * p0, &s1[q], &c1[q]);   // half-angle for RY layer 1
        __sincosf(p1, &Ss[q], &Cc[q]);          // full angle for M = C*Z - S*X
    }

    // Per-qubit single-qubit states phi_q and boundary factors r_q
    float ar_[NQ], ai_[NQ], br_[NQ], bi_[NQ], r_[NQ];
#pragma unroll
    for (int q = 0; q < NQ; q++) {
        float xv = x[b * NQ + q];
        float sx, cx;
        __sincosf(0.5f * xv, &sx, &cx);
        ar_[q] = c1[q] * cx;   ai_[q] = s1[q] * sx;    // phi0 = c1*cx + i*s1*sx
        br_[q] = s1[q] * cx;   bi_[q] = -c1[q] * sx;   // phi1 = s1*cx - i*c1*sx
        r_[q]  = 2.0f * c1[q] * s1[q] * (cx * cx - sx * sx);  // sin(p0)*cos(x)
    }

    // Hermitian 2x2 recursion state: W = [[w00, u],[conj(u), w11]],
    // w00/w11 real, u = ur + i*ui.
    float w00 = 1.0f, w11 = 0.0f, ur = 0.0f, ui = 0.0f;

#pragma unroll
    for (int q = 0; q < NQ; q++) {
        float ar = ar_[q], ai = ai_[q], br = br_[q], bi = bi_[q];

        // T = W * Phi   (Phi = [[a,b],[b,a]])
        float T00r = w00 * ar + ur * br - ui * bi;
        float T00i = w00 * ai + ur * bi + ui * br;
        float T01r = w00 * br + ur * ar - ui * ai;
        float T01i = w00 * bi + ur * ai + ui * ar;
        float T10r = ur * ar + ui * ai + w11 * br;
        float T10i = ur * ai - ui * ar + w11 * bi;
        float T11r = ur * br + ui * bi + w11 * ar;
        float T11i = ur * bi - ui * br + w11 * ai;

        // Y = conj(Phi) * T ; Y is Hermitian (keep Y00,Y11 real parts + Y01)
        float Y00 = ar * T00r + ai * T00i + br * T10r + bi * T10i;
        float Y11 = br * T01r + bi * T01i + ar * T11r + ai * T11i;
        float Y01r = ar * T01r + ai * T01i + br * T11r + bi * T11i;
        float Y01i = ar * T01i - ai * T01r + br * T11i - bi * T11r;

        // W = M (hadamard) Y,  M = [[C, -S],[-S, -C]]
        w00 =  Cc[q] * Y00;
        w11 = -Cc[q] * Y11;
        ur  = -Ss[q] * Y01r;
        ui  = -Ss[q] * Y01i;

        float rho = (q < NQ - 1) ? r_[q + 1] : 1.0f;
        out[b * NQ + q] = w00 + w11 + 2.0f * rho * ur;
    }
}

extern "C" void kernel_launch(void* const* d_in, const int* in_sizes, int n_in,
                              void* d_out, int out_size) {
    const float* x      = (const float*)d_in[0];   // (B, 14) float32
    const float* params = (const float*)d_in[1];   // (28,)   float32
    float* out = (float*)d_out;                    // (B, 14) float32

    int B = in_sizes[0] / NQ;
    int threads = 128;
    int blocks = (B + threads - 1) / threads;
    quantum_gate_kernel<<<blocks, threads>>>(x, params, out, B);
}

// round 5
// speedup vs baseline: 1.0048x; 1.0048x over previous
#include <cuda_runtime.h>

#define NQ 14
#define BLK 128

// Analytic transfer-matrix evaluation of the QuantumGate circuit.
//
// The CNOT chain (control w -> target w+1, increasing w) is the basis
// permutation P: b'_k = XOR_{j<=k} b_j. State before the first chain is a
// product state |psi1> = (x)_q phi_q,
//   phi_q = RY(p0_q) RX(x_q)|0> = [c1*cx + i*s1*sx,  s1*cx - i*c1*sx].
// Final state = P U2 P |psi1>, U2 = (x) RY(p1_q). With P^t Z_w P = Z_0..Z_w
// and RY^t Z RY = cos(p1) Z - sin(p1) X =: M_q, each expectation is a
// bond-dim-2 Hermitian transfer-matrix recursion:
//   W_{-1} = E00
//   W_q    = M_q (Hadamard) ( conj(Phi_q) W_{q-1} Phi_q ),  Phi=[[a,b],[b,a]]
//   <Z_w>  = W_w[00] + W_w[11] + rho_w * 2*Re(W_w[01])
//   rho_w  = sin(p0_{w+1})*cos(x_{w+1}) for w<13;  rho_13 = 1.

__global__ void __launch_bounds__(BLK)
quantum_gate_kernel(const float* __restrict__ x,
                    const float* __restrict__ params,
                    float* __restrict__ out, int B)
{
    __shared__ float sx[BLK * NQ];   // staged inputs  (7168 B)
    __shared__ float so[BLK * NQ];   // staged outputs (7168 B)

    const int blockBase = blockIdx.x * BLK;           // first batch element
    const int nElem     = min(BLK, B - blockBase);    // elements this block
    const int nFloats   = nElem * NQ;

    // ---- Coalesced staging of x into SMEM ----
    const float* gx = x + (size_t)blockBase * NQ;
    if (nFloats == BLK * NQ) {
        const float4* g4 = (const float4*)gx;         // block base is 16B-aligned
        float4* s4 = (float4*)sx;
#pragma unroll
        for (int i = threadIdx.x; i < (BLK * NQ) / 4; i += BLK)
            s4[i] = g4[i];
    } else {
        for (int i = threadIdx.x; i < nFloats; i += BLK)
            sx[i] = gx[i];
    }

    // ---- Shared-parameter trig (uniform across threads; overlaps load wait) ----
    float c1[NQ], s1[NQ], Cc[NQ], Ss[NQ];
#pragma unroll
    for (int q = 0; q < NQ; q++) {
        float p0 = __ldg(&params[q]);
        float p1 = __ldg(&params[NQ + q]);
        __sincosf(0.5f * p0, &s1[q], &c1[q]);   // half-angle for RY layer 1
        __sincosf(p1, &Ss[q], &Cc[q]);          // full angle: M = C*Z - S*X
    }

    __syncthreads();

    if (threadIdx.x < nElem) {
        const float* xv = &sx[threadIdx.x * NQ];
        float* ov = &so[threadIdx.x * NQ];

        // Per-qubit single-qubit states phi_q and boundary factors r_q
        float ar_[NQ], ai_[NQ], br_[NQ], bi_[NQ], r_[NQ];
#pragma unroll
        for (int q = 0; q < NQ; q++) {
            float sxv, cxv;
            __sincosf(0.5f * xv[q], &sxv, &cxv);
            ar_[q] = c1[q] * cxv;  ai_[q] = s1[q] * sxv;   // phi0
            br_[q] = s1[q] * cxv;  bi_[q] = -c1[q] * sxv;  // phi1
            r_[q]  = 2.0f * c1[q] * s1[q] * (cxv * cxv - sxv * sxv); // sin(p0)cos(x)
        }

        // Hermitian 2x2 recursion: W = [[w00, u],[conj(u), w11]], u = ur + i*ui
        float w00 = 1.0f, w11 = 0.0f, ur = 0.0f, ui = 0.0f;

#pragma unroll
        for (int q = 0; q < NQ; q++) {
            float ar = ar_[q], ai = ai_[q], br = br_[q], bi = bi_[q];

            // T = W * Phi   (Phi = [[a,b],[b,a]])
            float T00r = w00 * ar + ur * br - ui * bi;
            float T00i = w00 * ai + ur * bi + ui * br;
            float T01r = w00 * br + ur * ar - ui * ai;
            float T01i = w00 * bi + ur * ai + ui * ar;
            float T10r = ur * ar + ui * ai + w11 * br;
            float T10i = ur * ai - ui * ar + w11 * bi;
            float T11r = ur * br + ui * bi + w11 * ar;
            float T11i = ur * bi - ui * br + w11 * ai;

            // Y = conj(Phi) * T (Hermitian: keep real diagonals + Y01)
            float Y00  = ar * T00r + ai * T00i + br * T10r + bi * T10i;
            float Y11  = br * T01r + bi * T01i + ar * T11r + ai * T11i;
            float Y01r = ar * T01r + ai * T01i + br * T11r + bi * T11i;
            float Y01i = ar * T01i - ai * T01r + br * T11i - bi * T11r;

            // W = M (hadamard) Y,  M = [[C, -S],[-S, -C]]
            w00 =  Cc[q] * Y00;
            w11 = -Cc[q] * Y11;
            ur  = -Ss[q] * Y01r;
            ui  = -Ss[q] * Y01i;

            float rho = (q < NQ - 1) ? r_[q + 1] : 1.0f;
            ov[q] = fmaf(2.0f * rho, ur, w00 + w11);
        }
    }

    __syncthreads();

    // ---- Coalesced writeback ----
    float* go = out + (size_t)blockBase * NQ;
    if (nFloats == BLK * NQ) {
        const float4* s4 = (const float4*)so;
        float4* g4 = (float4*)go;
#pragma unroll
        for (int i = threadIdx.x; i < (BLK * NQ) / 4; i += BLK)
            g4[i] = s4[i];
    } else {
        for (int i = threadIdx.x; i < nFloats; i += BLK)
            go[i] = so[i];
    }
}

extern "C" void kernel_launch(void* const* d_in, const int* in_sizes, int n_in,
                              void* d_out, int out_size) {
    const float* x      = (const float*)d_in[0];   // (B, 14) float32
    const float* params = (const float*)d_in[1];   // (28,)   float32
    float* out = (float*)d_out;                    // (B, 14) float32

    int B = in_sizes[0] / NQ;
    int blocks = (B + BLK - 1) / BLK;
    quantum_gate_kernel<<<blocks, BLK>>>(x, params, out, B);
}

// round 6
// speedup vs baseline: 1.0097x; 1.0049x over previous
#include <cuda_runtime.h>

#define NQ  14
#define BLK 128

// Analytic evaluation of the QuantumGate circuit via a 4-real-variable
// transfer recursion (derivation in R3/R4; here further reduced).
//
// Per qubit q define (shared: cp=cos p0, sp=sin p0, C=cos p1, S=sin p1;
// per-thread: cx=cos x_q, sx=sin x_q):
//   D   = cp*cx            ( = |phi0|^2 - |phi1|^2 )
//   gr2 = sp*cx            ( = 2*Re(phi0* phi1) )
//   2*Im(phi0* phi1) = -sx
// State (S1, S2, u2r, u2i) = (w00+w11, w00-w11, 2*ur, 2*ui), init (1,1,0,0):
//   S1' = C*(D*S2 + sx*u2i)
//   S2' = C*(S1 + gr2*u2r)
//   u2r' = -S*(gr2*S1 + u2r)
//   u2i' = -S*(D*u2i - sx*S2)
//   <Z_q> = S1' + rho_q * u2r',  rho_q = gr2[q+1] (rho_{13} = 1)

__global__ void __launch_bounds__(BLK)
quantum_gate_kernel(const float* __restrict__ x,
                    const float* __restrict__ params,
                    float* __restrict__ out, int B)
{
    __shared__ float s_sin[2 * NQ];
    __shared__ float s_cos[2 * NQ];

    // One sincos per parameter, computed once per block.
    if (threadIdx.x < 2 * NQ) {
        float p = params[threadIdx.x];
        __sincosf(p, &s_sin[threadIdx.x], &s_cos[threadIdx.x]);
    }
    __syncthreads();

    const int b = blockIdx.x * BLK + threadIdx.x;
    if (b >= B) return;

    // ---- Load this element's 14 angles (7x LDG.64, 8B-aligned) ----
    float xv[NQ];
    {
        const float2* gx = (const float2*)(x + (size_t)b * NQ);
#pragma unroll
        for (int i = 0; i < NQ / 2; i++) {
            float2 v = gx[i];
            xv[2 * i] = v.x;
            xv[2 * i + 1] = v.y;
        }
    }

    // ---- Per-qubit derived quantities (independent; MUFU overlaps) ----
    float D_[NQ], gr2_[NQ], sx_[NQ];
#pragma unroll
    for (int q = 0; q < NQ; q++) {
        float sxv, cxv;
        __sincosf(xv[q], &sxv, &cxv);
        D_[q]   = s_cos[q] * cxv;   // cos(p0)*cos(x)
        gr2_[q] = s_sin[q] * cxv;   // sin(p0)*cos(x)
        sx_[q]  = sxv;
    }

    // ---- 4-variable serial recursion ----
    float S1 = 1.0f, S2 = 1.0f, u2r = 0.0f, u2i = 0.0f;
    float o[NQ];
#pragma unroll
    for (int q = 0; q < NQ; q++) {
        const float C  = s_cos[NQ + q];
        const float Sn = -s_sin[NQ + q];
        const float D = D_[q], g = gr2_[q], sx = sx_[q];

        float nS1  = C  * fmaf(D, S2, sx * u2i);
        float nS2  = C  * fmaf(g, u2r, S1);
        float nu2r = Sn * fmaf(g, S1, u2r);
        float nu2i = Sn * fmaf(D, u2i, -sx * S2);

        S1 = nS1; S2 = nS2; u2r = nu2r; u2i = nu2i;

        float rho = (q < NQ - 1) ? gr2_[q + 1] : 1.0f;
        o[q] = fmaf(rho, u2r, S1);
    }

    // ---- Write back (7x STG.64) ----
    {
        float2* go = (float2*)(out + (size_t)b * NQ);
#pragma unroll
        for (int i = 0; i < NQ / 2; i++) {
            float2 v;
            v.x = o[2 * i];
            v.y = o[2 * i + 1];
            go[i] = v;
        }
    }
}

extern "C" void kernel_launch(void* const* d_in, const int* in_sizes, int n_in,
                              void* d_out, int out_size) {
    const float* x      = (const float*)d_in[0];   // (B, 14) float32
    const float* params = (const float*)d_in[1];   // (28,)   float32
    float* out = (float*)d_out;                    // (B, 14) float32

    int B = in_sizes[0] / NQ;
    int blocks = (B + BLK - 1) / BLK;
    quantum_gate_kernel<<<blocks, BLK>>>(x, params, out, B);
}

// round 7
// speedup vs baseline: 1.0505x; 1.0404x over previous
#include <cuda_runtime.h>

#define NQ  14
#define BLK 128

// Analytic evaluation of the QuantumGate circuit via a 4-real-variable
// transfer recursion (derivation R3-R6).
//
// Per qubit q (shared: cp=cos p0, sp=sin p0, C=cos p1, S=sin p1;
// per-thread: cx=cos x_q, sx=sin x_q):
//   D = cp*cx,  g = sp*cx,  state (S1,S2,u2r,u2i) init (1,1,0,0):
//   S1' = C*(D*S2 + sx*u2i)        u2r' = -S*(g*S1 + u2r)
//   S2' = C*(S1 + g*u2r)           u2i' = -S*(D*u2i - sx*S2)
//   <Z_q> = S1' + rho*u2r',  rho = sp[q+1]*cx[q+1]  (rho_13 = 1)

__global__ void __launch_bounds__(BLK)
quantum_gate_kernel(const float* __restrict__ x,
                    const float* __restrict__ params,
                    float* __restrict__ out, int B)
{
    __shared__ float s_sin[2 * NQ];
    __shared__ float s_cos[2 * NQ];

    const int b = blockIdx.x * BLK + threadIdx.x;

    // ---- Issue x loads FIRST (independent of params path; overlaps it) ----
    float xv[NQ];
    {
        const float2* gx = (const float2*)(x + (size_t)b * NQ);
#pragma unroll
        for (int i = 0; i < NQ / 2; i++) {
            float2 v = gx[i];          // 7x LDG.64, fully parallel (MLP=7)
            xv[2 * i] = v.x;
            xv[2 * i + 1] = v.y;
        }
    }

    // ---- Param trig: one sincos per parameter, once per block ----
    if (threadIdx.x < 2 * NQ) {
        float p = __ldg(&params[threadIdx.x]);
        __sincosf(p, &s_sin[threadIdx.x], &s_cos[threadIdx.x]);
    }

    // ---- Per-thread x trig BEFORE the barrier (overlaps barrier wait) ----
    float cx_[NQ], sx_[NQ];
#pragma unroll
    for (int q = 0; q < NQ; q++)
        __sincosf(xv[q], &sx_[q], &cx_[q]);

    __syncthreads();

    // ---- 4-variable serial recursion; store pairs as they complete ----
    float S1 = 1.0f, S2 = 1.0f, u2r = 0.0f, u2i = 0.0f;
    float2* go = (float2*)(out + (size_t)b * NQ);
    float o_prev = 0.0f;

#pragma unroll
    for (int q = 0; q < NQ; q++) {
        const float C  = s_cos[NQ + q];
        const float Sn = -s_sin[NQ + q];
        const float cx = cx_[q], sx = sx_[q];
        const float D = s_cos[q] * cx;      // cos(p0)*cos(x)
        const float g = s_sin[q] * cx;      // sin(p0)*cos(x)

        float nS1  = C  * fmaf(D, S2, sx * u2i);
        float nS2  = C  * fmaf(g, u2r, S1);
        float nu2r = Sn * fmaf(g, S1, u2r);
        float nu2i = Sn * fmaf(D, u2i, -sx * S2);

        S1 = nS1; S2 = nS2; u2r = nu2r; u2i = nu2i;

        float rho = (q < NQ - 1) ? s_sin[q + 1] * cx_[q + 1] : 1.0f;
        float oq = fmaf(rho, u2r, S1);

        if (q & 1) {
            float2 v; v.x = o_prev; v.y = oq;
            go[q >> 1] = v;                  // STG.64 issued as soon as ready
        } else {
            o_prev = oq;
        }
    }
}

extern "C" void kernel_launch(void* const* d_in, const int* in_sizes, int n_in,
                              void* d_out, int out_size) {
    const float* x      = (const float*)d_in[0];   // (B, 14) float32
    const float* params = (const float*)d_in[1];   // (28,)   float32
    float* out = (float*)d_out;                    // (B, 14) float32

    int B = in_sizes[0] / NQ;
    int blocks = (B + BLK - 1) / BLK;              // B=4096 -> 32 blocks
    quantum_gate_kernel<<<blocks, BLK>>>(x, params, out, B);
}

// round 8
// speedup vs baseline: 1.1429x; 1.0879x over previous
#include <cuda_runtime.h>

#define NQ  14
#define BLK 32          // single-warp CTAs: BAR floor = 3 cyc, no cross-warp wait

// Analytic evaluation of the QuantumGate circuit via a 4-real-variable
// transfer recursion (derivation R3-R6).
//
// Per qubit q (shared: cp=cos p0, sp=sin p0, C=cos p1, S=sin p1;
// per-thread: cx=cos x_q, sx=sin x_q):
//   D = cp*cx,  g = sp*cx,  state (S1,S2,u2r,u2i) init (1,1,0,0):
//   S1' = C*(D*S2 + sx*u2i)        u2r' = -S*(g*S1 + u2r)
//   S2' = C*(S1 + g*u2r)           u2i' = -S*(D*u2i - sx*S2)
//   <Z_q> = S1' + rho*u2r',  rho = sp[q+1]*cx[q+1]  (rho_13 = 1)

__global__ void __launch_bounds__(BLK)
quantum_gate_kernel(const float* __restrict__ x,
                    const float* __restrict__ params,
                    float* __restrict__ out, int B)
{
    __shared__ float s_sin[2 * NQ];
    __shared__ float s_cos[2 * NQ];

    const int b = blockIdx.x * BLK + threadIdx.x;

    // ---- Issue x loads FIRST (7x LDG.64, MLP=7; overlaps the params leg) ----
    float xv[NQ];
    {
        const float2* gx = (const float2*)(x + (size_t)b * NQ);
#pragma unroll
        for (int i = 0; i < NQ / 2; i++) {
            float2 v = gx[i];
            xv[2 * i] = v.x;
            xv[2 * i + 1] = v.y;
        }
    }

    // ---- Param trig: 28 lanes of this warp, one sincos each ----
    if (threadIdx.x < 2 * NQ) {
        float p = __ldg(&params[threadIdx.x]);
        __sincosf(p, &s_sin[threadIdx.x], &s_cos[threadIdx.x]);
    }

    // ---- Per-thread x trig BEFORE the barrier (overlaps its wait) ----
    float cx_[NQ], sx_[NQ];
#pragma unroll
    for (int q = 0; q < NQ; q++)
        __sincosf(xv[q], &sx_[q], &cx_[q]);

    __syncthreads();   // nw=1: ~3-cycle floor, also drains the STS

    // ---- 4-variable serial recursion; store pairs as they complete ----
    float S1 = 1.0f, S2 = 1.0f, u2r = 0.0f, u2i = 0.0f;
    float2* go = (float2*)(out + (size_t)b * NQ);
    float o_prev = 0.0f;

#pragma unroll
    for (int q = 0; q < NQ; q++) {
        const float C  = s_cos[NQ + q];
        const float Sn = -s_sin[NQ + q];
        const float cx = cx_[q], sx = sx_[q];
        const float D = s_cos[q] * cx;      // cos(p0)*cos(x)
        const float g = s_sin[q] * cx;      // sin(p0)*cos(x)

        float nS1  = C  * fmaf(D, S2, sx * u2i);
        float nS2  = C  * fmaf(g, u2r, S1);
        float nu2r = Sn * fmaf(g, S1, u2r);
        float nu2i = Sn * fmaf(D, u2i, -sx * S2);

        S1 = nS1; S2 = nS2; u2r = nu2r; u2i = nu2i;

        float rho = (q < NQ - 1) ? s_sin[q + 1] * cx_[q + 1] : 1.0f;
        float oq = fmaf(rho, u2r, S1);

        if (q & 1) {
            float2 v; v.x = o_prev; v.y = oq;
            go[q >> 1] = v;                  // STG.64 issued as soon as ready
        } else {
            o_prev = oq;
        }
    }
}

extern "C" void kernel_launch(void* const* d_in, const int* in_sizes, int n_in,
                              void* d_out, int out_size) {
    const float* x      = (const float*)d_in[0];   // (B, 14) float32
    const float* params = (const float*)d_in[1];   // (28,)   float32
    float* out = (float*)d_out;                    // (B, 14) float32

    int B = in_sizes[0] / NQ;
    int blocks = (B + BLK - 1) / BLK;              // B=4096 -> 128 CTAs
    quantum_gate_kernel<<<blocks, BLK>>>(x, params, out, B);
}